// round 14
// baseline (speedup 1.0000x reference)
#include <cuda_runtime.h>
#include <cuda_bf16.h>

// 4096 possible 12-bit rows -> 32 floats each = 512 KB LUT in device global.
__device__ float g_lut[4096 * 32];

#define ROWS_PER_BLOCK 256
#define THREADS 256

// ---- LUT build kernel: 128 blocks x 128 threads = 16384 (b, s) items ----
__global__ __launch_bounds__(128)
void build_lut_kernel(const float* __restrict__ pat,
                      const float* __restrict__ pos,
                      const int*   __restrict__ conn)
{
    __shared__ int s_conn[240];
    for (int i = threadIdx.x; i < 240; i += 128)
        s_conn[i] = __ldg(&conn[i]);
    __syncthreads();

    const int idx = blockIdx.x * 128 + threadIdx.x;
    const int b = idx >> 2;
    const int s = idx & 3;

    const int bits3n = 3 * (s + 1);
    const int paddr  = b & ((1 << bits3n) - 1);   // last 3n columns, MSB-first

    float out[8];
    int pb = 0;
#pragma unroll
    for (int j = 0; j < 3; j++) {
        float v = __ldg(&pat[(s * 3 + j) * 4096 + paddr]);
        int bit = (v > 0.5f) ? 1 : 0;
        out[j]  = (float)bit;
        pb |= bit << j;
    }

    const int in_bits = bits3n + 3;
    const int nb      = (in_bits < 12) ? in_bits : 12;

    int addrs[5];
#pragma unroll
    for (int k = 0; k < 5; k++) {
        int addr = 0;
        for (int j = 0; j < nb; j++) {
            int c   = s_conn[(s * 5 + k) * 12 + j] % in_bits;
            int bit = (c < bits3n) ? ((paddr >> (bits3n - 1 - c)) & 1)
                                   : ((pb >> (c - bits3n)) & 1);
            addr |= bit << j;
        }
        addrs[k] = addr;
    }
#pragma unroll
    for (int k = 0; k < 5; k++)
        out[3 + k] = __ldg(&pos[(s * 5 + k) * 4096 + addrs[k]]);

    float4* dst = (float4*)&g_lut[b * 32 + s * 8];
    dst[0] = ((const float4*)out)[0];
    dst[1] = ((const float4*)out)[1];
}

// ---- Gather kernel: 256 rows/block, 2 batches of MLP=4, 32-reg budget ----
__global__ __launch_bounds__(THREADS, 8)
void gather_kernel(const int* __restrict__ tb,
                   float* __restrict__ out,
                   int nrows)
{
    __shared__ int s_bits[ROWS_PER_BLOCK * 12];   // 12288 B
    __shared__ int s_idx[ROWS_PER_BLOCK];         // 1024 B

    const int tid      = threadIdx.x;
    const int row_base = blockIdx.x * ROWS_PER_BLOCK;
    const int rows     = min(ROWS_PER_BLOCK, nrows - row_base);
    if (rows <= 0) return;

    // Stage 1: coalesced int4 loads (rows*12 divisible by 4).
    {
        const int n_int4 = (rows * 12) >> 2;              // 768 for full block
        const int4* src  = (const int4*)(tb + (size_t)row_base * 12);
        int4* dst        = (int4*)s_bits;
        for (int i = tid; i < n_int4; i += THREADS)
            dst[i] = __ldcs(src + i);
    }
    __syncthreads();

    // Stage 2: pack 12 bits MSB-first per row (one row per thread).
    if (tid < rows) {
        const int* r = &s_bits[tid * 12];
        int b = 0;
#pragma unroll
        for (int c = 0; c < 12; c++)
            b |= r[c] << (11 - c);
        s_idx[tid] = b;
    }
    __syncthreads();

    // Stage 3: 8 float4 chunks per row; two batches of 4 (MLP=4 each),
    // fully coalesced streaming stores.
    float4* out4 = (float4*)out + (size_t)row_base * 8;

    if (rows == ROWS_PER_BLOCK) {
#pragma unroll
        for (int h = 0; h < 2; h++) {
            float4 v[4];
#pragma unroll
            for (int j = 0; j < 4; j++) {
                const int t     = h * 4 * THREADS + tid + j * THREADS;
                const int row   = t >> 3;
                const int chunk = t & 7;
                v[j] = __ldg((const float4*)&g_lut[s_idx[row] * 32] + chunk);
            }
#pragma unroll
            for (int j = 0; j < 4; j++)
                __stcs(&out4[h * 4 * THREADS + tid + j * THREADS], v[j]);
        }
    } else {
        const int ntasks = rows * 8;
        for (int t = tid; t < ntasks; t += THREADS) {
            const int row   = t >> 3;
            const int chunk = t & 7;
            float4 v = __ldg((const float4*)&g_lut[s_idx[row] * 32] + chunk);
            __stcs(&out4[t], v);
        }
    }
}

extern "C" void kernel_launch(void* const* d_in, const int* in_sizes, int n_in,
                              void* d_out, int out_size)
{
    const int*   tb   = (const int*)  d_in[0];  // type_bits      (B, 12) i32
    const float* pat  = (const float*)d_in[1];  // pattern_tables (4,3,4096) f32
    const float* pos  = (const float*)d_in[2];  // position_tables(4,5,4096) f32
    const int*   conn = (const int*)  d_in[3];  // position_conn  (4,5,12) i32
    float*       out  = (float*)d_out;          // (B, 4, 8) f32

    int nrows   = in_sizes[0] / 12;
    int nblocks = (nrows + ROWS_PER_BLOCK - 1) / ROWS_PER_BLOCK;

    build_lut_kernel<<<128, 128>>>(pat, pos, conn);
    gather_kernel<<<nblocks, THREADS>>>(tb, out, nrows);
}

// round 15
// speedup vs baseline: 1.0367x; 1.0367x over previous
#include <cuda_runtime.h>
#include <cuda_bf16.h>

// 4096 possible 12-bit rows -> 32 floats each = 512 KB LUT in device global.
__device__ float g_lut[4096 * 32];
__device__ unsigned int g_done = 0;   // builder blocks completed
__device__ unsigned int g_exit = 0;   // blocks finished (counter reset)

#define ROWS_PER_BLOCK 256
#define THREADS 256
#define NBUILD  64        // 64 blocks x 256 threads = 16384 (b,s) items

// Compute one (b, s) LUT entry (8 floats). conn staged in smem by caller.
__device__ __forceinline__ void build_lut_item(int idx,
                                               const float* __restrict__ pat,
                                               const float* __restrict__ pos,
                                               const int*   __restrict__ s_conn)
{
    const int b = idx >> 2;
    const int s = idx & 3;

    const int bits3n = 3 * (s + 1);
    const int paddr  = b & ((1 << bits3n) - 1);   // last 3n columns, MSB-first

    float out[8];
    int pb = 0;
#pragma unroll
    for (int j = 0; j < 3; j++) {
        float v = __ldg(&pat[(s * 3 + j) * 4096 + paddr]);
        int bit = (v > 0.5f) ? 1 : 0;
        out[j]  = (float)bit;
        pb |= bit << j;
    }

    const int in_bits = bits3n + 3;
    const int nb      = (in_bits < 12) ? in_bits : 12;

    int addrs[5];
#pragma unroll
    for (int k = 0; k < 5; k++) {
        int addr = 0;
        for (int j = 0; j < nb; j++) {
            int c   = s_conn[(s * 5 + k) * 12 + j] % in_bits;
            int bit = (c < bits3n) ? ((paddr >> (bits3n - 1 - c)) & 1)
                                   : ((pb >> (c - bits3n)) & 1);
            addr |= bit << j;
        }
        addrs[k] = addr;
    }
#pragma unroll
    for (int k = 0; k < 5; k++)
        out[3 + k] = __ldg(&pos[(s * 5 + k) * 4096 + addrs[k]]);

    float4* dst = (float4*)&g_lut[b * 32 + s * 8];
    dst[0] = ((const float4*)out)[0];
    dst[1] = ((const float4*)out)[1];
}

// Fused kernel, one launch.
//   bid < 64: build 256 LUT items, release-publish (one atomic per block).
//   All blocks: stage1 (input staging) + stage2 (pack) BEFORE the gate.
//   Gate: tid0 RELAXED spin on g_done + bar.sync. No acquire, no fence:
//     - no SM reads g_lut pre-gate, so no stale L1 lines can exist;
//     - in-order issue puts post-gate LUT LDGs after the observed flag;
//     - builder's release-atomic puts LUT stores in L2 before the flag.
//   This avoids the per-block L1D invalidation that sank R4/R5/R11.
__global__ __launch_bounds__(THREADS, 8)
void fused_kernel(const int* __restrict__ tb,
                  float* __restrict__ out,
                  int nrows,
                  const float* __restrict__ pat,
                  const float* __restrict__ pos,
                  const int*   __restrict__ conn)
{
    __shared__ int s_bits[ROWS_PER_BLOCK * 12];   // 12288 B
    __shared__ int s_idx[ROWS_PER_BLOCK];         // 1024 B
    __shared__ int s_conn[240];                   // builders only

    const int tid = threadIdx.x;
    const int bid = blockIdx.x;

    // ---- Builder role ----
    if (bid < NBUILD) {
        if (tid < 240) s_conn[tid] = __ldg(&conn[tid]);
        __syncthreads();
        build_lut_item(bid * THREADS + tid, pat, pos, s_conn);
        __syncthreads();
        if (tid == 0) {
            unsigned int one = 1u, ignored;
            asm volatile("atom.add.release.gpu.u32 %0, [%1], %2;"
                         : "=r"(ignored) : "l"(&g_done), "r"(one) : "memory");
        }
    }

    const int row_base = bid * ROWS_PER_BLOCK;
    const int rows     = min(ROWS_PER_BLOCK, nrows - row_base);

    if (rows > 0) {
        // Stage 1: coalesced int4 loads (rows*12 divisible by 4).
        {
            const int n_int4 = (rows * 12) >> 2;          // 768 full block
            const int4* src  = (const int4*)(tb + (size_t)row_base * 12);
            int4* dst        = (int4*)s_bits;
            for (int i = tid; i < n_int4; i += THREADS)
                dst[i] = __ldcs(src + i);
        }
        __syncthreads();

        // Stage 2: pack 12 bits MSB-first per row.
        if (tid < rows) {
            const int* r = &s_bits[tid * 12];
            int b = 0;
#pragma unroll
            for (int c = 0; c < 12; c++)
                b |= r[c] << (11 - c);
            s_idx[tid] = b;
        }

        // ---- LUT gate: RELAXED spin (no L1 invalidation) + bar ----
        if (tid == 0) {
            unsigned int v;
            do {
                asm volatile("ld.relaxed.gpu.u32 %0, [%1];"
                             : "=r"(v) : "l"(&g_done) : "memory");
                if (v >= NBUILD) break;
                __nanosleep(64);
            } while (true);
        }
        __syncthreads();   // also publishes stage-2 smem for stage3

        // Stage 3: 8 float4 chunks per row; 2 batches of MLP=4;
        // fully coalesced streaming stores.
        float4* out4 = (float4*)out + (size_t)row_base * 8;

        if (rows == ROWS_PER_BLOCK) {
#pragma unroll
            for (int h = 0; h < 2; h++) {
                float4 v[4];
#pragma unroll
                for (int j = 0; j < 4; j++) {
                    const int t     = h * 4 * THREADS + tid + j * THREADS;
                    const int row   = t >> 3;
                    const int chunk = t & 7;
                    v[j] = __ldg((const float4*)&g_lut[s_idx[row] * 32] + chunk);
                }
#pragma unroll
                for (int j = 0; j < 4; j++)
                    __stcs(&out4[h * 4 * THREADS + tid + j * THREADS], v[j]);
            }
        } else {
            const int ntasks = rows * 8;
            for (int t = tid; t < ntasks; t += THREADS) {
                const int row   = t >> 3;
                const int chunk = t & 7;
                float4 v = __ldg((const float4*)&g_lut[s_idx[row] * 32] + chunk);
                __stcs(&out4[t], v);
            }
        }
    }

    // ---- Exit accounting: last block resets counters for next replay ----
    // Every block increments g_exit only after it has passed its gate, so
    // resetting g_done here cannot race any still-spinning block.
    if (tid == 0) {
        unsigned int t = atomicAdd(&g_exit, 1u);
        if (t == gridDim.x - 1) {
            g_done = 0;     // visible at kernel-completion boundary
            g_exit = 0;
        }
    }
}

extern "C" void kernel_launch(void* const* d_in, const int* in_sizes, int n_in,
                              void* d_out, int out_size)
{
    const int*   tb   = (const int*)  d_in[0];  // type_bits      (B, 12) i32
    const float* pat  = (const float*)d_in[1];  // pattern_tables (4,3,4096) f32
    const float* pos  = (const float*)d_in[2];  // position_tables(4,5,4096) f32
    const int*   conn = (const int*)  d_in[3];  // position_conn  (4,5,12) i32
    float*       out  = (float*)d_out;          // (B, 4, 8) f32

    int nrows   = in_sizes[0] / 12;
    int nblocks = (nrows + ROWS_PER_BLOCK - 1) / ROWS_PER_BLOCK;

    fused_kernel<<<nblocks, THREADS>>>(tb, out, nrows, pat, pos, conn);
}